// round 6
// baseline (speedup 1.0000x reference)
#include <cuda_runtime.h>

// out[n, p] = sum_f matrix[p, f] * nf_perm[n, f]
// nf_perm[n] = (F0, F3, F1, F2),  F = field[batch[n]]
//
// The generator's matrix has exactly one nonzero per row, so each output
// float is coef[p] * F[comp[p]]. Decoded once per thread from the matrix
// (generic, exact). The component selection is folded into the LOAD ADDRESS:
// per-thread byte offsets off[j] in {0,4,8,12} into the 16-byte field row,
// so the inner loop is 4 scalar LDGs + 4 FMULs + 1 STG.128 -- no SEL chains
// (R4's 42.8% ALU), no 16-float matrix in registers (R3's regs=40/occ=56%).
//
// Layout: 8 lanes per node; lane-group quad = tid&7 owns output floats
// [4q,4q+4) as one float4 -> warp STG.128s cover 512 contiguous bytes.
// 2 elements per thread, index + field loads front-batched for MLP.

__global__ __launch_bounds__(256, 8) void dgto_kernel(
    const int*  __restrict__ batch,
    const char* __restrict__ field,    // [n_graphs] rows of 16 bytes
    const float4* __restrict__ matrix, // 32 rows
    float4*     __restrict__ out,      // [n_nodes * 8]
    int total)                         // n_nodes * 8
{
    const int tid  = threadIdx.x;
    const int p0   = blockIdx.x * 512 + tid;   // element 0; element 1 = p0+256
    const int quad = tid & 7;                  // invariant (512 % 8 == 0)

    // Decode (coef, byte-offset) for this thread's 4 matrix rows.
    // val = m.x*F0 + m.y*F3 + m.z*F1 + m.w*F2  ->  offsets 0,12,4,8.
    float coef[4];
    int   off[4];
#pragma unroll
    for (int j = 0; j < 4; j++) {
        const float4 m = __ldg(&matrix[quad * 4 + j]);
        coef[j] = m.x + m.y + m.z + m.w;        // the single nonzero
        off[j]  = (m.y != 0.0f) ? 12
                : (m.z != 0.0f) ? 4
                : (m.w != 0.0f) ? 8
                :                 0;
    }

    const int p1 = p0 + 256;
    const bool v0 = (p0 < total);
    const bool v1 = (p1 < total);

    // Front-batch gather indices.
    const int b0 = v0 ? __ldg(&batch[p0 >> 3]) : 0;
    const int b1 = v1 ? __ldg(&batch[p1 >> 3]) : 0;
    const char* fp0 = field + ((long long)b0 << 4);
    const char* fp1 = field + ((long long)b1 << 4);

    // Front-batch all 8 scalar field loads (same L2-resident line per node;
    // lanes 0..7 of each octet share the node -> requests coalesce/broadcast).
    float f0[4], f1[4];
#pragma unroll
    for (int j = 0; j < 4; j++) f0[j] = __ldg((const float*)(fp0 + off[j]));
#pragma unroll
    for (int j = 0; j < 4; j++) f1[j] = __ldg((const float*)(fp1 + off[j]));

    if (v0) {
        float4 r;
        r.x = coef[0] * f0[0];
        r.y = coef[1] * f0[1];
        r.z = coef[2] * f0[2];
        r.w = coef[3] * f0[3];
        __stcs(&out[p0], r);   // streaming store: keep field table in L2
    }
    if (v1) {
        float4 r;
        r.x = coef[0] * f1[0];
        r.y = coef[1] * f1[1];
        r.z = coef[2] * f1[2];
        r.w = coef[3] * f1[3];
        __stcs(&out[p1], r);
    }
}

extern "C" void kernel_launch(void* const* d_in, const int* in_sizes, int n_in,
                              void* d_out, int out_size)
{
    const int*    batch  = (const int*)d_in[0];
    // d_in[1] = positions (unused by the reference output)
    const char*   field  = (const char*)d_in[2];
    const float4* matrix = (const float4*)d_in[3];
    float4*       out    = (float4*)d_out;

    const int n_nodes = in_sizes[0];
    const int total   = n_nodes * 8;           // float4 outputs
    const int grid    = (total + 511) / 512;   // 512 outputs per block

    dgto_kernel<<<grid, 256>>>(batch, field, matrix, out, total);
}

// round 7
// speedup vs baseline: 2.0054x; 2.0054x over previous
#include <cuda_runtime.h>

// out[n, p] = sum_f matrix[p, f] * nf_perm[n, f]
// nf_perm[n] = (F0, F3, F1, F2),  F = field[batch[n]]
//
// Proven-best structure (R3): 8 lanes per node, quad = lane&7 owns output
// floats [4q,4q+4) as one float4 (warp STG.128s cover 512 contiguous bytes);
// persistent grid-stride with quad invariant; 4 matrix rows register-resident;
// dense FFMA (no SEL chains); __stcs streaming stores keep the 1.6 MB field
// table L2-resident.
//
// R6 deltas: grid = 148*6 = exactly one resident wave at regs<=42
// (no stranded partial second wave -> achieved occ ~= theoretical 75%), and
// software-pipelined batch-index prefetch (removes batch-LDG latency from the
// steady-state dependency chain; field gathers issue at loop top).

__global__ __launch_bounds__(256, 6) void dgto_kernel(
    const int*    __restrict__ batch,
    const float4* __restrict__ field,   // [n_graphs] rows of 4 floats
    const float4* __restrict__ matrix,  // 32 rows of 4 floats
    float4*       __restrict__ out,     // [n_nodes * 8] float4
    int total)                          // n_nodes * 8
{
    const int stride = gridDim.x * blockDim.x;   // multiple of 8
    int p = blockIdx.x * blockDim.x + threadIdx.x;

    const int quad = p & 7;  // loop-invariant
    const float4 m0 = __ldg(&matrix[quad * 4 + 0]);
    const float4 m1 = __ldg(&matrix[quad * 4 + 1]);
    const float4 m2 = __ldg(&matrix[quad * 4 + 2]);
    const float4 m3 = __ldg(&matrix[quad * 4 + 3]);

    // Prologue: indices for the first pair.
    int b0 = 0, b1 = 0;
    if (p < total)          b0 = __ldg(&batch[p >> 3]);
    if (p + stride < total) b1 = __ldg(&batch[(p + stride) >> 3]);

    while (p + stride < total) {
        // Field gathers for the current pair issue immediately (indices were
        // prefetched last iteration).
        const float4 f0 = __ldg(&field[b0]);
        const float4 f1 = __ldg(&field[b1]);

        // Prefetch next pair's indices while f0/f1 are in flight.
        const int pn = p + 2 * stride;
        int nb0 = 0, nb1 = 0;
        if (pn < total)          nb0 = __ldg(&batch[pn >> 3]);
        if (pn + stride < total) nb1 = __ldg(&batch[(pn + stride) >> 3]);

        // permuted node field: (x, w, y, z)
        float4 r0, r1;
        r0.x = m0.x * f0.x + m0.y * f0.w + m0.z * f0.y + m0.w * f0.z;
        r0.y = m1.x * f0.x + m1.y * f0.w + m1.z * f0.y + m1.w * f0.z;
        r0.z = m2.x * f0.x + m2.y * f0.w + m2.z * f0.y + m2.w * f0.z;
        r0.w = m3.x * f0.x + m3.y * f0.w + m3.z * f0.y + m3.w * f0.z;

        r1.x = m0.x * f1.x + m0.y * f1.w + m0.z * f1.y + m0.w * f1.z;
        r1.y = m1.x * f1.x + m1.y * f1.w + m1.z * f1.y + m1.w * f1.z;
        r1.z = m2.x * f1.x + m2.y * f1.w + m2.z * f1.y + m2.w * f1.z;
        r1.w = m3.x * f1.x + m3.y * f1.w + m3.z * f1.y + m3.w * f1.z;

        __stcs(&out[p],          r0);
        __stcs(&out[p + stride], r1);

        b0 = nb0; b1 = nb1;
        p  = pn;
    }

    // Tail: at most one element per thread.
    if (p < total) {
        const float4 f = __ldg(&field[b0]);
        float4 r;
        r.x = m0.x * f.x + m0.y * f.w + m0.z * f.y + m0.w * f.z;
        r.y = m1.x * f.x + m1.y * f.w + m1.z * f.y + m1.w * f.z;
        r.z = m2.x * f.x + m2.y * f.w + m2.z * f.y + m2.w * f.z;
        r.w = m3.x * f.x + m3.y * f.w + m3.z * f.y + m3.w * f.z;
        __stcs(&out[p], r);
    }
}

extern "C" void kernel_launch(void* const* d_in, const int* in_sizes, int n_in,
                              void* d_out, int out_size)
{
    const int*    batch  = (const int*)d_in[0];
    // d_in[1] = positions (unused by the reference output)
    const float4* field  = (const float4*)d_in[2];
    const float4* matrix = (const float4*)d_in[3];
    float4*       out    = (float4*)d_out;

    const int n_nodes = in_sizes[0];
    const int total   = n_nodes * 8;   // float4 outputs

    // Exactly one resident wave: 6 blocks/SM (regs<=42) x 148 SMs.
    // 888*256 = 227,328 threads; stride is a multiple of 8 so quad is
    // loop-invariant per thread.
    const int block = 256;
    const int grid  = 148 * 6;

    dgto_kernel<<<grid, block>>>(batch, field, matrix, out, total);
}